// round 2
// baseline (speedup 1.0000x reference)
#include <cuda_runtime.h>
#include <cstdint>

// ---------------------------------------------------------------------------
// SymmetrizeRotavg:
//   scaled[n]   = inv_lat[b(n)]^T @ forces[n]
//   acc[symm_map[n,o]] += rot[o] @ scaled[n]   (o = 0..O-1)
//   out[n]      = lat[b(n)]^T @ (acc[n] / O)
//
// Design: the scatter is the whole kernel (N*O = 50.3M red.global.add.v4.f32,
// ~1.29 cyc/lane REDG spread floor). Stage-1 math is recomputed inline inside
// the scatter (cheap, hides the g_scaled round trip); symm_map is streamed
// with evict-first hints to keep the 16MB accumulator L2-resident.
// ---------------------------------------------------------------------------

#define MAX_N (1 << 20)   // N = 1,048,576 for this problem
#define MAX_O 64

__device__ float4 g_acc[MAX_N];

// Zero the accumulator (needed every launch: graph replays must be
// deterministic). Pure float4 store stream.
__global__ __launch_bounds__(256) void k_zero(int N)
{
    int i = blockIdx.x * blockDim.x + threadIdx.x;
    int stride = gridDim.x * blockDim.x;
    float4 z = make_float4(0.f, 0.f, 0.f, 0.f);
    for (; i < N; i += stride) g_acc[i] = z;
}

__device__ __forceinline__ void red_add_v4(float4* p, float x, float y, float z)
{
    asm volatile(
        "{\n\t"
        ".reg .u64 ga;\n\t"
        "cvta.to.global.u64 ga, %0;\n\t"
        "red.global.add.v4.f32 [ga], {%1, %2, %3, %4};\n\t"
        "}"
        :: "l"(p), "f"(x), "f"(y), "f"(z), "f"(0.0f)
        : "memory");
}

// Streaming (evict-first) int4 load for the one-shot symm_map stream.
__device__ __forceinline__ int4 ldcs_int4(const int* p)
{
    int4 v;
    asm volatile("ld.global.cs.v4.s32 {%0,%1,%2,%3}, [%4];"
                 : "=r"(v.x), "=r"(v.y), "=r"(v.z), "=r"(v.w)
                 : "l"(p));
    return v;
}

// Fused scatter: one thread handles one n and 4 consecutive ops.
// Recomputes scaled = inv_lat^T f inline (forces/inv_lat loads are
// broadcast-shared by the 12 threads per n -> L1 hits).
__global__ __launch_bounds__(256) void k_scatter4(
    const float* __restrict__ inv_lat,  // (B,3,3)
    const float* __restrict__ forces,   // (N,3)
    const float* __restrict__ gops,     // (O,4,4)
    const int*   __restrict__ smap,     // (N,O)
    int N, int O, int A)
{
    __shared__ float srot[MAX_O * 9];
    for (int t = threadIdx.x; t < O * 9; t += blockDim.x) {
        int o = t / 9;
        int e = t - o * 9;
        int i = e / 3;
        int j = e - i * 3;
        srot[t] = gops[o * 16 + i * 4 + j];
    }
    __syncthreads();

    int per_n = O >> 2;  // groups of 4 ops (O % 4 == 0)
    long long idx = (long long)blockIdx.x * blockDim.x + threadIdx.x;
    long long total = (long long)N * per_n;
    if (idx >= total) return;
    int n = (int)(idx / per_n);
    int k = (int)(idx - (long long)n * per_n);

    // scaled = inv_lat[b]^T @ forces[n]
    int b = n / A;
    float f0 = __ldg(forces + 3 * n + 0);
    float f1 = __ldg(forces + 3 * n + 1);
    float f2 = __ldg(forces + 3 * n + 2);
    const float* M = inv_lat + 9 * b;   // M[j*3+i]
    float sx = __ldg(M + 0) * f0 + __ldg(M + 3) * f1 + __ldg(M + 6) * f2;
    float sy = __ldg(M + 1) * f0 + __ldg(M + 4) * f1 + __ldg(M + 7) * f2;
    float sz = __ldg(M + 2) * f0 + __ldg(M + 5) * f1 + __ldg(M + 8) * f2;

    // 128-bit coalesced streaming load of 4 targets
    int4 t4 = ldcs_int4(smap + (long long)n * O + k * 4);
    int tgt[4] = { t4.x, t4.y, t4.z, t4.w };

#pragma unroll
    for (int r = 0; r < 4; r++) {
        int o = k * 4 + r;
        const float* R = srot + o * 9;   // R[i*3+j]
        float x = R[0] * sx + R[1] * sy + R[2] * sz;
        float y = R[3] * sx + R[4] * sy + R[5] * sz;
        float z = R[6] * sx + R[7] * sy + R[8] * sz;
        red_add_v4(&g_acc[tgt[r]], x, y, z);
    }
}

// Fallback scatter (O not a multiple of 4): one thread per (n,o).
__global__ __launch_bounds__(256) void k_scatter1(
    const float* __restrict__ inv_lat,
    const float* __restrict__ forces,
    const float* __restrict__ gops,
    const int*   __restrict__ smap,
    int N, int O, int A)
{
    __shared__ float srot[MAX_O * 9];
    for (int t = threadIdx.x; t < O * 9; t += blockDim.x) {
        int o = t / 9;
        int e = t - o * 9;
        int i = e / 3;
        int j = e - i * 3;
        srot[t] = gops[o * 16 + i * 4 + j];
    }
    __syncthreads();

    long long idx = (long long)blockIdx.x * blockDim.x + threadIdx.x;
    long long total = (long long)N * O;
    if (idx >= total) return;
    int n = (int)(idx / O);
    int o = (int)(idx - (long long)n * O);

    int b = n / A;
    float f0 = __ldg(forces + 3 * n + 0);
    float f1 = __ldg(forces + 3 * n + 1);
    float f2 = __ldg(forces + 3 * n + 2);
    const float* M = inv_lat + 9 * b;
    float sx = __ldg(M + 0) * f0 + __ldg(M + 3) * f1 + __ldg(M + 6) * f2;
    float sy = __ldg(M + 1) * f0 + __ldg(M + 4) * f1 + __ldg(M + 7) * f2;
    float sz = __ldg(M + 2) * f0 + __ldg(M + 5) * f1 + __ldg(M + 8) * f2;

    int tgt = smap[(long long)n * O + o];
    const float* R = srot + o * 9;
    float x = R[0] * sx + R[1] * sy + R[2] * sz;
    float y = R[3] * sx + R[4] * sy + R[5] * sz;
    float z = R[6] * sx + R[7] * sy + R[8] * sz;
    red_add_v4(&g_acc[tgt], x, y, z);
}

// Stage 3 vectorized: 4 atoms per thread, float4 in / 3x float4 out.
// Requires A % 4 == 0 so all 4 atoms share the same lattice.
__global__ __launch_bounds__(256) void k_final4(
    const float* __restrict__ lat,
    float* __restrict__ out,
    int N4, int A, float inv_count)
{
    int q = blockIdx.x * blockDim.x + threadIdx.x;
    if (q >= N4) return;
    int n0 = q * 4;
    int b = n0 / A;
    const float* L = lat + 9 * b;   // L[j*3+i]
    float L00 = L[0], L01 = L[1], L02 = L[2];
    float L10 = L[3], L11 = L[4], L12 = L[5];
    float L20 = L[6], L21 = L[7], L22 = L[8];

    float r[12];
#pragma unroll
    for (int t = 0; t < 4; t++) {
        float4 a = g_acc[n0 + t];
        float s0 = a.x * inv_count;
        float s1 = a.y * inv_count;
        float s2 = a.z * inv_count;
        r[t * 3 + 0] = L00 * s0 + L10 * s1 + L20 * s2;
        r[t * 3 + 1] = L01 * s0 + L11 * s1 + L21 * s2;
        r[t * 3 + 2] = L02 * s0 + L12 * s1 + L22 * s2;
    }
    float4* dst = reinterpret_cast<float4*>(out + (long long)q * 12);
    dst[0] = make_float4(r[0], r[1], r[2],  r[3]);
    dst[1] = make_float4(r[4], r[5], r[6],  r[7]);
    dst[2] = make_float4(r[8], r[9], r[10], r[11]);
}

// Scalar fallback final.
__global__ __launch_bounds__(256) void k_final1(
    const float* __restrict__ lat,
    float* __restrict__ out,
    int N, int A, float inv_count)
{
    int n = blockIdx.x * blockDim.x + threadIdx.x;
    if (n >= N) return;
    int b = n / A;
    float4 a = g_acc[n];
    float s0 = a.x * inv_count;
    float s1 = a.y * inv_count;
    float s2 = a.z * inv_count;
    const float* L = lat + 9 * b;
    out[3 * n + 0] = L[0] * s0 + L[3] * s1 + L[6] * s2;
    out[3 * n + 1] = L[1] * s0 + L[4] * s1 + L[7] * s2;
    out[3 * n + 2] = L[2] * s0 + L[5] * s1 + L[8] * s2;
}

extern "C" void kernel_launch(void* const* d_in, const int* in_sizes, int n_in,
                              void* d_out, int out_size)
{
    const float* lattices     = (const float*)d_in[0];  // (B,3,3)
    const float* inv_lattices = (const float*)d_in[1];  // (B,3,3)
    const float* forces       = (const float*)d_in[2];  // (N,3)
    // d_in[3] = num_atoms (int64, uniform A)
    const float* general_ops  = (const float*)d_in[4];  // (O,4,4)
    const int*   symm_map     = (const int*)d_in[5];    // (N,O)
    // d_in[6] = num_general_ops (int64, uniform O)

    int B = in_sizes[0] / 9;
    int N = in_sizes[2] / 3;
    int O = in_sizes[4] / 16;
    int A = N / B;

    float* out = (float*)d_out;
    const int TPB = 256;

    // Zero accumulator (grid-stride, sized for full-chip residency)
    k_zero<<<1184, TPB>>>(N);

    if ((O & 3) == 0) {
        long long total = (long long)N * (O >> 2);
        int blocks = (int)((total + TPB - 1) / TPB);
        k_scatter4<<<blocks, TPB>>>(inv_lattices, forces, general_ops,
                                    symm_map, N, O, A);
    } else {
        long long total = (long long)N * O;
        int blocks = (int)((total + TPB - 1) / TPB);
        k_scatter1<<<blocks, TPB>>>(inv_lattices, forces, general_ops,
                                    symm_map, N, O, A);
    }

    float inv_count = 1.0f / (float)O;
    if ((A & 3) == 0 && (N & 3) == 0) {
        int N4 = N / 4;
        k_final4<<<(N4 + TPB - 1) / TPB, TPB>>>(lattices, out, N4, A, inv_count);
    } else {
        k_final1<<<(N + TPB - 1) / TPB, TPB>>>(lattices, out, N, A, inv_count);
    }
}